// round 9
// baseline (speedup 1.0000x reference)
#include <cuda_runtime.h>
#include <math.h>
#include <stdint.h>

#define H 1024
#define P 8

#define BK 32
#define NSTAGE 3
#define NC (H / BK)          // 32 K-chunks
#define SA 36                // A smem row stride (floats)
#define SBS 136              // B smem row stride (floats), BN=128 always

// ---------------- scratch ----------------
__device__ float g_w[P];
__device__ float g_cc[2];
__device__ float g_Weff[H * H];
__device__ float g_M[H * H];

// ---------------- helpers ----------------
__device__ __forceinline__ uint32_t smem_u32(const void* p) {
    uint32_t a;
    asm("{ .reg .u64 t; cvta.to.shared.u64 t, %1; cvt.u32.u64 %0, t; }" : "=r"(a) : "l"(p));
    return a;
}
#define CPASYNC16(s, g) asm volatile("cp.async.cg.shared.global [%0], [%1], 16;" :: "r"(s), "l"(g) : "memory")
#define CPCOMMIT()      asm volatile("cp.async.commit_group;" ::: "memory")
#define CPWAIT2()       asm volatile("cp.async.wait_group 2;" ::: "memory")

__device__ __forceinline__ void mma_tf32(float* d, const uint32_t* a, const uint32_t* b) {
    asm volatile(
        "mma.sync.aligned.m16n8k8.row.col.f32.tf32.tf32.f32 "
        "{%0,%1,%2,%3}, {%4,%5,%6,%7}, {%8,%9}, {%0,%1,%2,%3};"
        : "+f"(d[0]), "+f"(d[1]), "+f"(d[2]), "+f"(d[3])
        : "r"(a[0]), "r"(a[1]), "r"(a[2]), "r"(a[3]), "r"(b[0]), "r"(b[1]));
}

// ---------------- kernel A: scalars ----------------
__global__ void prep_kernel(const float* __restrict__ J, const float* __restrict__ t) {
    if (threadIdx.x != 0) return;
    float tv = t[0];
    float alpha = expf(-tv / 51.0f);
    alpha = fminf(fmaxf(alpha, 0.0f), 1.0f);
    float phase = 2.0f * 3.14159265358979323846f * 20.0f * tv / 1000.0f;
    float w[P];
#pragma unroll
    for (int j = 0; j < P; j++) w[j] = 0.0f;
    for (int i = 0; i < P; i++) {
        float row[P];
        float mx = -1e30f;
#pragma unroll
        for (int j = 0; j < P; j++) {
            float js = 0.5f * (J[i * P + j] + J[j * P + i]);
            row[j] = cosf(phase * js);
            mx = fmaxf(mx, row[j]);
        }
        float s = 0.0f;
#pragma unroll
        for (int j = 0; j < P; j++) { row[j] = expf(row[j] - mx); s += row[j]; }
        float inv = 1.0f / s;
#pragma unroll
        for (int j = 0; j < P; j++) w[j] += row[j] * inv;
    }
#pragma unroll
    for (int j = 0; j < P; j++) g_w[j] = w[j];
    g_cc[0] = alpha * alpha / 64.0f;
    g_cc[1] = alpha * (1.0f - alpha) / 64.0f;
}

// ---------------- kernel B: Weff = sum_j w[j] * W_paths[j] ----------------
__global__ void weff_kernel(const float4* __restrict__ Wp) {
    int i = blockIdx.x * blockDim.x + threadIdx.x;
    float4 acc = make_float4(0.f, 0.f, 0.f, 0.f);
#pragma unroll
    for (int j = 0; j < P; j++) {
        float wj = g_w[j];
        float4 v = Wp[(size_t)j * (H * H / 4) + i];
        acc.x = fmaf(wj, v.x, acc.x);
        acc.y = fmaf(wj, v.y, acc.y);
        acc.z = fmaf(wj, v.z, acc.z);
        acc.w = fmaf(wj, v.w, acc.w);
    }
    ((float4*)g_Weff)[i] = acc;
}

// ---------------- tf32 mma.sync GEMM: C = A(MxK) @ B(Kx1024), BN=128 ----------------
// Warps: WM x WN grid of 8 warps; warp tile (BM/WM) x (128/WN); mma m16n8k8.
// Raw fp32 bits fed as tf32 (truncation) — no cvt in the hot loop.
// MODE 0: store C.  MODE 1: fused epilogue  out = cc0*sum_j w_j*coh + cc1*acc.
template <int BM, int WM, int WN, int MODE>
__global__ void __launch_bounds__(256) gemm_mma(const float* __restrict__ A,
                                                const float* __restrict__ Bm,
                                                float* __restrict__ C,
                                                const float* __restrict__ coh) {
    constexpr int BN = 128;
    constexpr int MT = BM / WM / 16;
    constexpr int NT = BN / WN / 8;
    constexpr int A_F = BM * SA;
    constexpr int B_F = BK * SBS;
    constexpr int STAGE_F = A_F + B_F;
    constexpr int IA = BM * 8 / 256;   // A float4 loads per thread
    constexpr int IB = BN * 8 / 256;   // B float4 loads per thread

    extern __shared__ float sm[];
    const int tid = threadIdx.x;
    const int wid = tid >> 5;
    const int lane = tid & 31;
    const int g = lane >> 2;
    const int tg = lane & 3;
    const int m0w = (wid % WM) * (BM / WM);
    const int n0w = (wid / WM) * (BN / WN);
    const int m0 = blockIdx.y * BM;
    const int n0 = blockIdx.x * BN;

    float acc[MT][NT][4];
#pragma unroll
    for (int mt = 0; mt < MT; mt++)
#pragma unroll
        for (int nt = 0; nt < NT; nt++)
#pragma unroll
            for (int q = 0; q < 4; q++) acc[mt][nt][q] = 0.0f;

    auto load_tile = [&](int c) {
        int s = c % NSTAGE;
        float* As = sm + s * STAGE_F;
        float* Bs = As + A_F;
        int k0 = c * BK;
#pragma unroll
        for (int i = 0; i < IA; i++) {
            int v = tid + i * 256;
            int row = v >> 3, c4 = v & 7;
            const float* src = A + (size_t)(m0 + row) * H + k0 + c4 * 4;
            CPASYNC16(smem_u32(As + row * SA + c4 * 4), src);
        }
#pragma unroll
        for (int i = 0; i < IB; i++) {
            int v = tid + i * 256;
            int row = v >> 5, c4 = v & 31;
            const float* src = Bm + (size_t)(k0 + row) * H + n0 + c4 * 4;
            CPASYNC16(smem_u32(Bs + row * SBS + c4 * 4), src);
        }
    };

#pragma unroll
    for (int c = 0; c < NSTAGE; c++) {
        load_tile(c);
        CPCOMMIT();
    }

    for (int c = 0; c < NC; c++) {
        int s = c % NSTAGE;
        const float* As = sm + s * STAGE_F;
        const float* Bs = As + A_F;
        CPWAIT2();
        __syncthreads();

        uint32_t af[2][MT][4], bf[2][NT][2];
        // fragment loader for k-slab ks into buffer bi (raw bits, no cvt)
        auto lf = [&](int ks, int bi) {
#pragma unroll
            for (int mt = 0; mt < MT; mt++) {
                const float* ap = As + (m0w + mt * 16 + g) * SA + ks * 8 + tg;
                af[bi][mt][0] = __float_as_uint(ap[0]);
                af[bi][mt][1] = __float_as_uint(ap[8 * SA]);
                af[bi][mt][2] = __float_as_uint(ap[4]);
                af[bi][mt][3] = __float_as_uint(ap[8 * SA + 4]);
            }
#pragma unroll
            for (int nt = 0; nt < NT; nt++) {
                const float* bp = Bs + (ks * 8 + tg) * SBS + n0w + nt * 8 + g;
                bf[bi][nt][0] = __float_as_uint(bp[0]);
                bf[bi][nt][1] = __float_as_uint(bp[4 * SBS]);
            }
        };

        lf(0, 0);
#pragma unroll
        for (int ks = 0; ks < 4; ks++) {
            if (ks < 3) lf(ks + 1, (ks + 1) & 1);
            int bi = ks & 1;
#pragma unroll
            for (int mt = 0; mt < MT; mt++)
#pragma unroll
                for (int nt = 0; nt < NT; nt++)
                    mma_tf32(acc[mt][nt], af[bi][mt], bf[bi][nt]);
        }

        __syncthreads();
        int nx = c + NSTAGE;
        if (nx < NC) load_tile(nx);
        CPCOMMIT();
    }

    // ---- epilogue ----
    if (MODE == 0) {
#pragma unroll
        for (int mt = 0; mt < MT; mt++) {
            int r0 = m0 + m0w + mt * 16 + g;
#pragma unroll
            for (int nt = 0; nt < NT; nt++) {
                int col = n0 + n0w + nt * 8 + 2 * tg;
                *(float2*)&C[(size_t)r0 * H + col] = make_float2(acc[mt][nt][0], acc[mt][nt][1]);
                *(float2*)&C[(size_t)(r0 + 8) * H + col] = make_float2(acc[mt][nt][2], acc[mt][nt][3]);
            }
        }
    } else {
        float wreg[P];
#pragma unroll
        for (int j = 0; j < P; j++) wreg[j] = g_w[j];
        float cc0 = g_cc[0], cc1 = g_cc[1];
#pragma unroll
        for (int mt = 0; mt < MT; mt++) {
#pragma unroll
            for (int half = 0; half < 2; half++) {
                int r = m0 + m0w + mt * 16 + g + half * 8;
                const float* crow = coh + (size_t)r * (P * H);
#pragma unroll
                for (int nt = 0; nt < NT; nt++) {
                    int col = n0 + n0w + nt * 8 + 2 * tg;
                    float sx = 0.f, sy = 0.f;
#pragma unroll
                    for (int j = 0; j < P; j++) {
                        float2 cv = *(const float2*)&crow[j * H + col];
                        sx = fmaf(wreg[j], cv.x, sx);
                        sy = fmaf(wreg[j], cv.y, sy);
                    }
                    float2 o;
                    o.x = fmaf(cc1, acc[mt][nt][half * 2 + 0], cc0 * sx);
                    o.y = fmaf(cc1, acc[mt][nt][half * 2 + 1], cc0 * sy);
                    *(float2*)&C[(size_t)r * H + col] = o;
                }
            }
        }
    }
}

// ---------------- launch ----------------
extern "C" void kernel_launch(void* const* d_in, const int* in_sizes, int n_in,
                              void* d_out, int out_size) {
    const float* x       = (const float*)d_in[0];
    const float* W_input = (const float*)d_in[1];
    const float* W_paths = (const float*)d_in[2];
    const float* J       = (const float*)d_in[3];
    const float* coh     = (const float*)d_in[4];
    const float* t       = (const float*)d_in[5];

    int B = in_sizes[0] / H;

    // gemm_c: BM=64 (16x8 = 128 CTAs, fills chip), warp grid 2m x 4n (32x32 tiles)
    constexpr int SMEM_C = NSTAGE * (64 * SA + BK * SBS) * 4;
    // gemm_d: BM=128, warp grid 4m x 2n (32x64 tiles)
    constexpr int SMEM_D = NSTAGE * (128 * SA + BK * SBS) * 4;

    cudaFuncSetAttribute((const void*)gemm_mma<64, 2, 4, 0>, cudaFuncAttributeMaxDynamicSharedMemorySize, SMEM_C);
    cudaFuncSetAttribute((const void*)gemm_mma<128, 4, 2, 1>, cudaFuncAttributeMaxDynamicSharedMemorySize, SMEM_D);

    float* Weff_p;
    float* M_p;
    cudaGetSymbolAddress((void**)&Weff_p, g_Weff);
    cudaGetSymbolAddress((void**)&M_p, g_M);

    prep_kernel<<<1, 32>>>(J, t);
    weff_kernel<<<(H * H / 4) / 256, 256>>>((const float4*)W_paths);
    // M = W_input @ Weff   (1024x1024x1024, 128 CTAs)
    gemm_mma<64, 2, 4, 0><<<dim3(H / 128, H / 64), 256, SMEM_C>>>(W_input, Weff_p, M_p, nullptr);
    // out = cc0*(w-weighted coherent sum) + cc1*(x @ M)   (2048x1024x1024, 128 CTAs)
    gemm_mma<128, 4, 2, 1><<<dim3(H / 128, B / 128), 256, SMEM_D>>>(x, M_p, (float*)d_out, coh);
}

// round 14
// speedup vs baseline: 1.6109x; 1.6109x over previous
#include <cuda_runtime.h>
#include <math.h>
#include <stdint.h>

#define H 1024
#define P 8

#define BK 32
#define NSTAGE 3
#define NC (H / BK)          // 32 K-chunks
#define SA 36                // A smem row stride (floats)

// ---------------- scratch ----------------
__device__ float g_w[P];
__device__ float g_cc[2];
__device__ float g_Weff[H * H];
__device__ float g_M[H * H];

// ---------------- helpers ----------------
__device__ __forceinline__ uint32_t smem_u32(const void* p) {
    uint32_t a;
    asm("{ .reg .u64 t; cvta.to.shared.u64 t, %1; cvt.u32.u64 %0, t; }" : "=r"(a) : "l"(p));
    return a;
}
#define CPASYNC16(s, g) asm volatile("cp.async.cg.shared.global [%0], [%1], 16;" :: "r"(s), "l"(g) : "memory")
#define CPCOMMIT()      asm volatile("cp.async.commit_group;" ::: "memory")
#define CPWAIT2()       asm volatile("cp.async.wait_group 2;" ::: "memory")

__device__ __forceinline__ void mma_tf32(float* d, const uint32_t* a, const uint32_t* b) {
    asm volatile(
        "mma.sync.aligned.m16n8k8.row.col.f32.tf32.tf32.f32 "
        "{%0,%1,%2,%3}, {%4,%5,%6,%7}, {%8,%9}, {%0,%1,%2,%3};"
        : "+f"(d[0]), "+f"(d[1]), "+f"(d[2]), "+f"(d[3])
        : "r"(a[0]), "r"(a[1]), "r"(a[2]), "r"(a[3]), "r"(b[0]), "r"(b[1]));
}

// ---------------- kernel A: scalars ----------------
__global__ void prep_kernel(const float* __restrict__ J, const float* __restrict__ t) {
    if (threadIdx.x != 0) return;
    float tv = t[0];
    float alpha = expf(-tv / 51.0f);
    alpha = fminf(fmaxf(alpha, 0.0f), 1.0f);
    float phase = 2.0f * 3.14159265358979323846f * 20.0f * tv / 1000.0f;
    float w[P];
#pragma unroll
    for (int j = 0; j < P; j++) w[j] = 0.0f;
    for (int i = 0; i < P; i++) {
        float row[P];
        float mx = -1e30f;
#pragma unroll
        for (int j = 0; j < P; j++) {
            float js = 0.5f * (J[i * P + j] + J[j * P + i]);
            row[j] = cosf(phase * js);
            mx = fmaxf(mx, row[j]);
        }
        float s = 0.0f;
#pragma unroll
        for (int j = 0; j < P; j++) { row[j] = expf(row[j] - mx); s += row[j]; }
        float inv = 1.0f / s;
#pragma unroll
        for (int j = 0; j < P; j++) w[j] += row[j] * inv;
    }
#pragma unroll
    for (int j = 0; j < P; j++) g_w[j] = w[j];
    g_cc[0] = alpha * alpha / 64.0f;
    g_cc[1] = alpha * (1.0f - alpha) / 64.0f;
}

// ---------------- kernel B: Weff = sum_j w[j] * W_paths[j] ----------------
__global__ void weff_kernel(const float4* __restrict__ Wp) {
    int i = blockIdx.x * blockDim.x + threadIdx.x;
    float4 acc = make_float4(0.f, 0.f, 0.f, 0.f);
#pragma unroll
    for (int j = 0; j < P; j++) {
        float wj = g_w[j];
        float4 v = Wp[(size_t)j * (H * H / 4) + i];
        acc.x = fmaf(wj, v.x, acc.x);
        acc.y = fmaf(wj, v.y, acc.y);
        acc.z = fmaf(wj, v.z, acc.z);
        acc.w = fmaf(wj, v.w, acc.w);
    }
    ((float4*)g_Weff)[i] = acc;
}

// ---------------- tf32 mma.sync GEMM: C = A(MxK) @ B(KxN), K=N=1024 ----------------
// Warps: WM x WN grid of 8 warps; warp tile (BM/WM) x (BN/WN); mma m16n8k8.
// Raw fp32 bits fed as tf32 (truncation, no cvt). R5-proven single-buffer schedule.
// MODE 0: store C.  MODE 1: fused epilogue  out = cc0*sum_j w_j*coh + cc1*acc.
template <int BM, int BN, int WM, int WN, int MODE>
__global__ void __launch_bounds__(256) gemm_mma(const float* __restrict__ A,
                                                const float* __restrict__ Bm,
                                                float* __restrict__ C,
                                                const float* __restrict__ coh) {
    constexpr int SBS = BN + 8;        // B smem stride: = 8 mod 32 -> conflict-free frags
    constexpr int MT = BM / WM / 16;
    constexpr int NT = BN / WN / 8;
    constexpr int A_F = BM * SA;
    constexpr int B_F = BK * SBS;
    constexpr int STAGE_F = A_F + B_F;
    constexpr int IA = BM * 8 / 256;   // A float4 loads per thread
    constexpr int IB = BN * 8 / 256;   // B float4 loads per thread
    constexpr int BN4 = BN / 4;

    extern __shared__ float sm[];
    const int tid = threadIdx.x;
    const int wid = tid >> 5;
    const int lane = tid & 31;
    const int g = lane >> 2;
    const int tg = lane & 3;
    const int m0w = (wid % WM) * (BM / WM);
    const int n0w = (wid / WM) * (BN / WN);
    const int m0 = blockIdx.y * BM;
    const int n0 = blockIdx.x * BN;

    float acc[MT][NT][4];
#pragma unroll
    for (int mt = 0; mt < MT; mt++)
#pragma unroll
        for (int nt = 0; nt < NT; nt++)
#pragma unroll
            for (int q = 0; q < 4; q++) acc[mt][nt][q] = 0.0f;

    auto load_tile = [&](int c) {
        int s = c % NSTAGE;
        float* As = sm + s * STAGE_F;
        float* Bs = As + A_F;
        int k0 = c * BK;
#pragma unroll
        for (int i = 0; i < IA; i++) {
            int v = tid + i * 256;
            int row = v >> 3, c4 = v & 7;
            const float* src = A + (size_t)(m0 + row) * H + k0 + c4 * 4;
            CPASYNC16(smem_u32(As + row * SA + c4 * 4), src);
        }
#pragma unroll
        for (int i = 0; i < IB; i++) {
            int v = tid + i * 256;
            int row = v / BN4, c4 = v % BN4;
            const float* src = Bm + (size_t)(k0 + row) * H + n0 + c4 * 4;
            CPASYNC16(smem_u32(Bs + row * SBS + c4 * 4), src);
        }
    };

#pragma unroll
    for (int c = 0; c < NSTAGE; c++) {
        load_tile(c);
        CPCOMMIT();
    }

    for (int c = 0; c < NC; c++) {
        int s = c % NSTAGE;
        const float* As = sm + s * STAGE_F;
        const float* Bs = As + A_F;
        CPWAIT2();
        __syncthreads();
#pragma unroll
        for (int ks = 0; ks < 4; ks++) {
            uint32_t af[MT][4];
#pragma unroll
            for (int mt = 0; mt < MT; mt++) {
                const float* ap = As + (m0w + mt * 16 + g) * SA + ks * 8 + tg;
                af[mt][0] = __float_as_uint(ap[0]);
                af[mt][1] = __float_as_uint(ap[8 * SA]);
                af[mt][2] = __float_as_uint(ap[4]);
                af[mt][3] = __float_as_uint(ap[8 * SA + 4]);
            }
            uint32_t bf[NT][2];
#pragma unroll
            for (int nt = 0; nt < NT; nt++) {
                const float* bp = Bs + (ks * 8 + tg) * SBS + n0w + nt * 8 + g;
                bf[nt][0] = __float_as_uint(bp[0]);
                bf[nt][1] = __float_as_uint(bp[4 * SBS]);
            }
#pragma unroll
            for (int mt = 0; mt < MT; mt++)
#pragma unroll
                for (int nt = 0; nt < NT; nt++)
                    mma_tf32(acc[mt][nt], af[mt], bf[nt]);
        }
        __syncthreads();
        int nx = c + NSTAGE;
        if (nx < NC) load_tile(nx);
        CPCOMMIT();
    }

    // ---- epilogue ----
    if (MODE == 0) {
#pragma unroll
        for (int mt = 0; mt < MT; mt++) {
            int r0 = m0 + m0w + mt * 16 + g;
#pragma unroll
            for (int nt = 0; nt < NT; nt++) {
                int col = n0 + n0w + nt * 8 + 2 * tg;
                *(float2*)&C[(size_t)r0 * H + col] = make_float2(acc[mt][nt][0], acc[mt][nt][1]);
                *(float2*)&C[(size_t)(r0 + 8) * H + col] = make_float2(acc[mt][nt][2], acc[mt][nt][3]);
            }
        }
    } else {
        float wreg[P];
#pragma unroll
        for (int j = 0; j < P; j++) wreg[j] = g_w[j];
        float cc0 = g_cc[0], cc1 = g_cc[1];
#pragma unroll
        for (int mt = 0; mt < MT; mt++) {
#pragma unroll
            for (int half = 0; half < 2; half++) {
                int r = m0 + m0w + mt * 16 + g + half * 8;
                const float* crow = coh + (size_t)r * (P * H);
#pragma unroll
                for (int nt = 0; nt < NT; nt++) {
                    int col = n0 + n0w + nt * 8 + 2 * tg;
                    float sx = 0.f, sy = 0.f;
#pragma unroll
                    for (int j = 0; j < P; j++) {
                        float2 cv = *(const float2*)&crow[j * H + col];
                        sx = fmaf(wreg[j], cv.x, sx);
                        sy = fmaf(wreg[j], cv.y, sy);
                    }
                    float2 o;
                    o.x = fmaf(cc1, acc[mt][nt][half * 2 + 0], cc0 * sx);
                    o.y = fmaf(cc1, acc[mt][nt][half * 2 + 1], cc0 * sy);
                    *(float2*)&C[(size_t)r * H + col] = o;
                }
            }
        }
    }
}

// ---------------- launch ----------------
extern "C" void kernel_launch(void* const* d_in, const int* in_sizes, int n_in,
                              void* d_out, int out_size) {
    const float* x       = (const float*)d_in[0];
    const float* W_input = (const float*)d_in[1];
    const float* W_paths = (const float*)d_in[2];
    const float* J       = (const float*)d_in[3];
    const float* coh     = (const float*)d_in[4];
    const float* t       = (const float*)d_in[5];

    int B = in_sizes[0] / H;

    // gemm_c: 64x64 tiles -> 16x16 = 256 CTAs; warps 2m x 4n (32x16 tiles)
    constexpr int SMEM_C = NSTAGE * (64 * SA + BK * (64 + 8)) * 4;
    // gemm_d: 128x64 tiles -> 16x16 = 256 CTAs; warps 4m x 2n (32x32 tiles)
    constexpr int SMEM_D = NSTAGE * (128 * SA + BK * (64 + 8)) * 4;

    cudaFuncSetAttribute((const void*)gemm_mma<64, 64, 2, 4, 0>, cudaFuncAttributeMaxDynamicSharedMemorySize, SMEM_C);
    cudaFuncSetAttribute((const void*)gemm_mma<128, 64, 4, 2, 1>, cudaFuncAttributeMaxDynamicSharedMemorySize, SMEM_D);

    float* Weff_p;
    float* M_p;
    cudaGetSymbolAddress((void**)&Weff_p, g_Weff);
    cudaGetSymbolAddress((void**)&M_p, g_M);

    prep_kernel<<<1, 32>>>(J, t);
    weff_kernel<<<(H * H / 4) / 256, 256>>>((const float4*)W_paths);
    // M = W_input @ Weff   (1024^3, 256 CTAs)
    gemm_mma<64, 64, 2, 4, 0><<<dim3(H / 64, H / 64), 256, SMEM_C>>>(W_input, Weff_p, M_p, nullptr);
    // out = cc0*(w-weighted coherent sum) + cc1*(x @ M)   (2048x1024x1024, 256 CTAs)
    gemm_mma<128, 64, 4, 2, 1><<<dim3(H / 64, B / 128), 256, SMEM_D>>>(x, M_p, (float*)d_out, coh);
}